// round 1
// baseline (speedup 1.0000x reference)
#include <cuda_runtime.h>

#define BB   8
#define NN   1024
#define FIN  25
#define HH   8
#define DD   16
#define TI   16          // rows per block in main kernel
#define CH   256         // j-chunk staged in smem
#define WH_STRIDE 20     // padded float stride for staged Wh rows (16 data + 4 pad)
#define NEG_INF -9.0e15f

// -------- device scratch (no allocations allowed) --------
__device__ float g_Wh[(size_t)BB*HH*NN*DD];   // 4 MB
__device__ float g_ei[(size_t)BB*HH*NN];
__device__ float g_ej[(size_t)BB*HH*NN];

// ============================================================
// Kernel A: Wh = einsum('bnf,hfd->bhnd'), ei/ej = Wh . a_src/dst
// grid: B * (N/32) = 256 blocks, 256 threads (32 nodes x 8 heads)
// ============================================================
__global__ __launch_bounds__(256) void gat_prep(const float* __restrict__ x,
                                                const float* __restrict__ W,
                                                const float* __restrict__ a) {
    __shared__ float s_W[HH * 401];   // [h][f*16+d], h-stride padded to 401 (bank spread)
    __shared__ float s_x[32 * FIN];
    __shared__ float s_a[HH * 32];

    int tid = threadIdx.x;
    int b  = blockIdx.x >> 5;        // 32 tiles per batch
    int nt = blockIdx.x & 31;
    int n0 = nt * 32;

    for (int idx = tid; idx < HH * 400; idx += 256) {
        int h = idx / 400, rem = idx - h * 400;
        s_W[h * 401 + rem] = W[idx];
    }
    s_a[tid] = a[tid];               // exactly 256 = H*2D
    for (int idx = tid; idx < 32 * FIN; idx += 256) {
        s_x[idx] = x[((size_t)b * NN + n0) * FIN + idx];  // 800 contiguous floats
    }
    __syncthreads();

    int nl = tid >> 3;               // 0..31 node within tile
    int h  = tid & 7;                // 0..7 head

    float wh[DD];
    #pragma unroll
    for (int d = 0; d < DD; d++) wh[d] = 0.f;

    const float* wbase = &s_W[h * 401];
    const float* xr    = &s_x[nl * FIN];
    #pragma unroll
    for (int f = 0; f < FIN; f++) {
        float xv = xr[f];
        #pragma unroll
        for (int d = 0; d < DD; d++) wh[d] += xv * wbase[f * 16 + d];
    }

    float e1 = 0.f, e2 = 0.f;
    #pragma unroll
    for (int d = 0; d < DD; d++) {
        e1 += wh[d] * s_a[h * 32 + d];
        e2 += wh[d] * s_a[h * 32 + 16 + d];
    }

    int n = n0 + nl;
    size_t base = ((size_t)(b * HH + h) * NN + n);
    float4* dst = (float4*)&g_Wh[base * DD];
    dst[0] = make_float4(wh[0],  wh[1],  wh[2],  wh[3]);
    dst[1] = make_float4(wh[4],  wh[5],  wh[6],  wh[7]);
    dst[2] = make_float4(wh[8],  wh[9],  wh[10], wh[11]);
    dst[3] = make_float4(wh[12], wh[13], wh[14], wh[15]);
    g_ei[base] = e1;
    g_ej[base] = e2;
}

// ============================================================
// Kernel B: masked softmax + alpha write + h' = alpha @ Wh (+relu)
// grid: B * (N/TI) = 512 blocks, 256 threads
// dyn smem: s_adj (TI*NN u8) | s_ej (NN f32) | s_alpha (TI*NN f32) | s_wh (CH*20 f32)
// ============================================================
extern __shared__ char dynsmem[];

__global__ __launch_bounds__(256) void gat_main(const int* __restrict__ adj,
                                                float* __restrict__ hprime,
                                                float* __restrict__ alpha) {
    unsigned char* s_adj = (unsigned char*)dynsmem;
    float* s_ej    = (float*)(dynsmem + TI * NN);
    float* s_alpha = s_ej + NN;
    float* s_wh    = s_alpha + TI * NN;

    int tid = threadIdx.x;
    int b  = blockIdx.x >> 6;        // 64 tiles of 16 rows
    int it = blockIdx.x & 63;
    int i0 = it * TI;

    // load adj rows i0..i0+15 as bytes (reused by ALL 8 heads)
    const int* arow = adj + ((size_t)b * NN + i0) * NN;
    for (int idx = tid; idx < TI * NN; idx += 256)
        s_adj[idx] = (unsigned char)(arow[idx] != 0);

    int warp = tid >> 5, lane = tid & 31;
    int js = tid & 15, dq = (tid >> 4) & 3, rq = tid >> 6;

    for (int h = 0; h < HH; h++) {
        size_t bh = (size_t)(b * HH + h);

        __syncthreads();  // guards s_adj (h==0) and s_ej/s_alpha reuse (h>0)
        for (int idx = tid; idx < NN; idx += 256)
            s_ej[idx] = g_ej[bh * NN + idx];
        __syncthreads();

        // ---- softmax: each warp owns rows (warp, warp+8) ----
        #pragma unroll
        for (int rr2 = 0; rr2 < 2; rr2++) {
            int r = warp + rr2 * 8;
            int i = i0 + r;
            float eiv = g_ei[bh * NN + i];
            const unsigned char* am = &s_adj[r * NN];
            float* srow = &s_alpha[r * NN];

            float m = NEG_INF;
            for (int j = lane; j < NN; j += 32) {
                float e = am[j] ? (eiv + s_ej[j]) : NEG_INF;
                m = fmaxf(m, e);
            }
            #pragma unroll
            for (int off = 16; off; off >>= 1)
                m = fmaxf(m, __shfl_xor_sync(0xffffffffu, m, off));

            float s = 0.f;
            for (int j = lane; j < NN; j += 32) {
                float e = am[j] ? (eiv + s_ej[j]) : NEG_INF;
                float p = __expf(e - m);
                srow[j] = p;
                s += p;
            }
            #pragma unroll
            for (int off = 16; off; off >>= 1)
                s += __shfl_xor_sync(0xffffffffu, s, off);
            float inv = 1.0f / s;

            float* grow = alpha + (bh * NN + i) * NN;
            for (int j = lane; j < NN; j += 32) {
                float av = srow[j] * inv;
                srow[j] = av;
                grow[j] = av;
            }
        }
        __syncthreads();

        // ---- AV: h'[i0+rq*4+rr][dq*4+dd] over j ≡ js (mod 16) ----
        float acc[4][4];
        #pragma unroll
        for (int rr = 0; rr < 4; rr++)
            #pragma unroll
            for (int dd = 0; dd < 4; dd++) acc[rr][dd] = 0.f;

        const float4* whp = (const float4*)&g_Wh[bh * NN * DD];
        for (int jc = 0; jc < NN; jc += CH) {
            // stage Wh chunk into padded smem
            for (int t = tid; t < CH * 4; t += 256) {
                float4 v = whp[jc * 4 + t];
                int cj = t >> 2, dd4 = t & 3;
                *(float4*)&s_wh[cj * WH_STRIDE + dd4 * 4] = v;
            }
            __syncthreads();
            for (int cj = js; cj < CH; cj += 16) {
                float4 w = *(const float4*)&s_wh[cj * WH_STRIDE + dq * 4];
                int jcol = jc + cj;
                #pragma unroll
                for (int rr = 0; rr < 4; rr++) {
                    float av = s_alpha[(rq * 4 + rr) * NN + jcol];
                    acc[rr][0] += av * w.x;
                    acc[rr][1] += av * w.y;
                    acc[rr][2] += av * w.z;
                    acc[rr][3] += av * w.w;
                }
            }
            __syncthreads();
        }

        // reduce across the 16 js lanes (butterfly within 16-lane halves)
        #pragma unroll
        for (int rr = 0; rr < 4; rr++)
            #pragma unroll
            for (int dd = 0; dd < 4; dd++) {
                float v = acc[rr][dd];
                #pragma unroll
                for (int off = 8; off; off >>= 1)
                    v += __shfl_xor_sync(0xffffffffu, v, off);
                acc[rr][dd] = v;
            }

        if (js == 0) {
            #pragma unroll
            for (int rr = 0; rr < 4; rr++) {
                int i = i0 + rq * 4 + rr;
                float* op = hprime + ((size_t)b * NN + i) * (HH * DD) + h * DD + dq * 4;
                float4 o = make_float4(fmaxf(acc[rr][0], 0.f), fmaxf(acc[rr][1], 0.f),
                                       fmaxf(acc[rr][2], 0.f), fmaxf(acc[rr][3], 0.f));
                *(float4*)op = o;
            }
        }
        // next head's leading __syncthreads guards s_alpha/s_ej overwrite
    }
}

// ============================================================
extern "C" void kernel_launch(void* const* d_in, const int* in_sizes, int n_in,
                              void* d_out, int out_size) {
    const float* x   = (const float*)d_in[0];   // (8,1024,25)
    const int*   adj = (const int*)  d_in[1];   // (8,1024,1024)
    const float* W   = (const float*)d_in[2];   // (8,25,16)
    const float* a   = (const float*)d_in[3];   // (8,32,1)

    float* out    = (float*)d_out;
    float* hprime = out;                                    // (8,1024,128)
    float* alpha  = out + (size_t)BB * NN * HH * DD;        // (8,8,1024,1024)

    static const int smem_bytes = TI * NN          // s_adj bytes
                                + NN * 4           // s_ej
                                + TI * NN * 4      // s_alpha
                                + CH * WH_STRIDE * 4;  // s_wh
    cudaFuncSetAttribute(gat_main, cudaFuncAttributeMaxDynamicSharedMemorySize, smem_bytes);

    gat_prep<<<BB * (NN / 32), 256>>>(x, W, a);
    gat_main<<<BB * (NN / TI), 256, smem_bytes>>>(adj, hprime, alpha);
}

// round 2
// speedup vs baseline: 1.8828x; 1.8828x over previous
#include <cuda_runtime.h>

#define BB   8
#define NN   1024
#define FIN  25
#define HH   8
#define DD   16

// -------- device scratch --------
__device__ float g_Wh[(size_t)BB*HH*NN*DD];     // (b,h,n,d) 4MB
__device__ float g_ej[(size_t)BB*HH*NN];        // (b,h,n)
__device__ float g_p [(size_t)BB*HH*NN];        // (b,h,n) 256KB
__device__ float g_Q [(size_t)BB*NN*128];       // (b,n,h*16+d) 4MB
__device__ float g_invS[(size_t)BB*NN*HH];      // (b,n,h) 256KB

// ---- f32x2 helpers (ptxas won't emit FFMA2 from C++) ----
__device__ __forceinline__ unsigned long long dup_f(float x) {
    unsigned long long r; unsigned u = __float_as_uint(x);
    asm("mov.b64 %0, {%1, %1};" : "=l"(r) : "r"(u));
    return r;
}
__device__ __forceinline__ void fma2(unsigned long long& d,
                                     unsigned long long a, unsigned long long b) {
    asm("fma.rn.f32x2 %0, %1, %2, %0;" : "+l"(d) : "l"(a), "l"(b));
}
__device__ __forceinline__ void unpack2(unsigned long long v, float& lo, float& hi) {
    asm("mov.b64 {%0, %1}, %2;" : "=f"(lo), "=f"(hi) : "l"(v));
}

// ============================================================
// Kernel 1: Wh = x@W per head, ej = Wh . a_dst
// grid 256 (b * 32 node-tiles), 256 threads (32 nodes x 8 heads)
// ============================================================
__global__ __launch_bounds__(256) void gat_prep(const float* __restrict__ x,
                                                const float* __restrict__ W,
                                                const float* __restrict__ a) {
    __shared__ float s_W[HH * 401];
    __shared__ float s_x[32 * FIN];
    __shared__ float s_a[HH * 32];

    int tid = threadIdx.x;
    int b  = blockIdx.x >> 5;
    int n0 = (blockIdx.x & 31) * 32;

    for (int idx = tid; idx < HH * 400; idx += 256) {
        int h = idx / 400, rem = idx - h * 400;
        s_W[h * 401 + rem] = W[idx];
    }
    s_a[tid] = a[tid];
    for (int idx = tid; idx < 32 * FIN; idx += 256)
        s_x[idx] = x[((size_t)b * NN + n0) * FIN + idx];
    __syncthreads();

    int nl = tid >> 3;
    int h  = tid & 7;

    float wh[DD];
    #pragma unroll
    for (int d = 0; d < DD; d++) wh[d] = 0.f;

    const float* wbase = &s_W[h * 401];
    const float* xr    = &s_x[nl * FIN];
    #pragma unroll
    for (int f = 0; f < FIN; f++) {
        float xv = xr[f];
        #pragma unroll
        for (int d = 0; d < DD; d++) wh[d] += xv * wbase[f * 16 + d];
    }

    float e2 = 0.f;
    #pragma unroll
    for (int d = 0; d < DD; d++) e2 += wh[d] * s_a[h * 32 + 16 + d];

    size_t base = ((size_t)(b * HH + h) * NN + n0 + nl);
    float4* dst = (float4*)&g_Wh[base * DD];
    dst[0] = make_float4(wh[0],  wh[1],  wh[2],  wh[3]);
    dst[1] = make_float4(wh[4],  wh[5],  wh[6],  wh[7]);
    dst[2] = make_float4(wh[8],  wh[9],  wh[10], wh[11]);
    dst[3] = make_float4(wh[12], wh[13], wh[14], wh[15]);
    g_ej[base] = e2;
}

// ============================================================
// Kernel 2: per (b,h): M = max_j ej, p = exp(ej-M), Q = p*Wh
// grid 64 (b*h), 256 threads (4 nodes each)
// ============================================================
__global__ __launch_bounds__(256) void gat_pexp() {
    __shared__ float wmax[8];
    int tid = threadIdx.x, lane = tid & 31, warp = tid >> 5;
    int bh = blockIdx.x, b = bh >> 3, h = bh & 7;

    float4 e = ((const float4*)(g_ej + (size_t)bh * NN))[tid];
    float m = fmaxf(fmaxf(e.x, e.y), fmaxf(e.z, e.w));
    #pragma unroll
    for (int off = 16; off; off >>= 1)
        m = fmaxf(m, __shfl_xor_sync(0xffffffffu, m, off));
    if (lane == 0) wmax[warp] = m;
    __syncthreads();
    float M = wmax[0];
    #pragma unroll
    for (int w = 1; w < 8; w++) M = fmaxf(M, wmax[w]);

    float4 p = make_float4(__expf(e.x - M), __expf(e.y - M),
                           __expf(e.z - M), __expf(e.w - M));
    ((float4*)(g_p + (size_t)bh * NN))[tid] = p;

    const float pv[4] = {p.x, p.y, p.z, p.w};
    #pragma unroll
    for (int k = 0; k < 4; k++) {
        int j = tid * 4 + k;
        const float4* wsrc = (const float4*)&g_Wh[((size_t)bh * NN + j) * DD];
        float4* qdst = (float4*)&g_Q[((size_t)b * NN + j) * 128 + h * DD];
        float pk = pv[k];
        #pragma unroll
        for (int q = 0; q < 4; q++) {
            float4 w = wsrc[q];
            qdst[q] = make_float4(w.x * pk, w.y * pk, w.z * pk, w.w * pk);
        }
    }
}

// ============================================================
// Kernel 3: H[i][c] = sum_j adj[i][j] * Q[j][c]   (c = 128 = h*16+d)
//           S[i][h] = sum_j adj[i][j] * p_h[j]
//           hprime  = relu(H * invS), g_invS written for kernel 4
// grid 256 (b * 32 row-tiles of 32 rows), 128 threads
// thread = (c4 0..31 [float4 col], rg 0..3 [8 rows each])
// ============================================================
extern __shared__ char dynsmem[];

__global__ __launch_bounds__(128) void gat_gemm(const int* __restrict__ adj,
                                                float* __restrict__ hprime) {
    float* sQ = (float*)dynsmem;            // [64][128]   32KB
    float* sM = sQ + 64 * 128;              // [4][64][8]   8KB (raw 0/1 masks)
    float* sP = sM + 4 * 64 * 8;            // [8][1024]   32KB
    float* sS = sP + 8 * NN;                // [32][8] invS 1KB

    int tid = threadIdx.x;
    int c4 = tid & 31, rg = tid >> 5;
    int b = blockIdx.x >> 5;
    int i0 = (blockIdx.x & 31) * 32;

    // persistent p for this batch
    for (int k = tid; k < 2048; k += 128)
        ((float4*)sP)[k] = ((const float4*)(g_p + (size_t)b * HH * NN))[k];

    unsigned long long acc[8][2];
    #pragma unroll
    for (int r = 0; r < 8; r++) { acc[r][0] = 0ull; acc[r][1] = 0ull; }

    for (int jc = 0; jc < NN; jc += 64) {
        __syncthreads();
        // stage Q chunk: 64 rows x 128 cols
        const float4* gq = (const float4*)(g_Q + ((size_t)b * NN + jc) * 128);
        #pragma unroll
        for (int k = 0; k < 16; k++)
            ((float4*)sQ)[k * 128 + tid] = gq[k * 128 + tid];
        // stage masks: rows i0..i0+31, cols jc..jc+63 -> sM[rg][jj][r8]
        #pragma unroll
        for (int k = 0; k < 4; k++) {
            int idx = k * 128 + tid;              // 0..511
            int row = idx >> 4, cc = (idx & 15) * 4;
            int4 av = *(const int4*)(adj + ((size_t)b * NN + i0 + row) * NN + jc + cc);
            float* base = sM + ((row >> 3) * 64 + cc) * 8 + (row & 7);
            base[0]  = (float)av.x;
            base[8]  = (float)av.y;
            base[16] = (float)av.z;
            base[24] = (float)av.w;
        }
        __syncthreads();

        const float* mrow = sM + rg * 64 * 8;
        #pragma unroll 4
        for (int jj = 0; jj < 64; jj++) {
            ulonglong2 qv = *(const ulonglong2*)&sQ[jj * 128 + c4 * 4];
            float4 ma = *(const float4*)&mrow[jj * 8];
            float4 mb = *(const float4*)&mrow[jj * 8 + 4];
            unsigned long long m0 = dup_f(ma.x), m1 = dup_f(ma.y);
            unsigned long long m2 = dup_f(ma.z), m3 = dup_f(ma.w);
            unsigned long long m4 = dup_f(mb.x), m5 = dup_f(mb.y);
            unsigned long long m6 = dup_f(mb.z), m7 = dup_f(mb.w);
            fma2(acc[0][0], m0, qv.x); fma2(acc[0][1], m0, qv.y);
            fma2(acc[1][0], m1, qv.x); fma2(acc[1][1], m1, qv.y);
            fma2(acc[2][0], m2, qv.x); fma2(acc[2][1], m2, qv.y);
            fma2(acc[3][0], m3, qv.x); fma2(acc[3][1], m3, qv.y);
            fma2(acc[4][0], m4, qv.x); fma2(acc[4][1], m4, qv.y);
            fma2(acc[5][0], m5, qv.x); fma2(acc[5][1], m5, qv.y);
            fma2(acc[6][0], m6, qv.x); fma2(acc[6][1], m6, qv.y);
            fma2(acc[7][0], m7, qv.x); fma2(acc[7][1], m7, qv.y);
        }
    }
    __syncthreads();

    // ---- S pass: warp w handles rows w, w+4, ..., w+28 ----
    int warp = tid >> 5, lane = tid & 31;
    for (int r = warp; r < 32; r += 4) {
        const int4* arow4 = (const int4*)(adj + ((size_t)b * NN + i0 + r) * NN);
        float s[8];
        #pragma unroll
        for (int h = 0; h < 8; h++) s[h] = 0.f;
        for (int j4 = lane; j4 < 256; j4 += 32) {
            int4 av = arow4[j4];
            float m0 = (float)av.x, m1 = (float)av.y;
            float m2 = (float)av.z, m3 = (float)av.w;
            int j = j4 * 4;
            #pragma unroll
            for (int h = 0; h < 8; h++) {
                float4 pv = *(const float4*)&sP[h * NN + j];
                s[h] += m0 * pv.x + m1 * pv.y + m2 * pv.z + m3 * pv.w;
            }
        }
        #pragma unroll
        for (int h = 0; h < 8; h++) {
            float v = s[h];
            #pragma unroll
            for (int off = 16; off; off >>= 1)
                v += __shfl_xor_sync(0xffffffffu, v, off);
            s[h] = v;
        }
        if (lane < 8)
            sS[r * 8 + lane] = (s[lane] > 0.f) ? (1.f / s[lane]) : (1.f / NN);
    }
    __syncthreads();

    // write invS for alpha kernel
    for (int k = tid; k < 256; k += 128)
        g_invS[((size_t)b * NN + i0) * 8 + k] = sS[k];

    // finalize hprime: head = c4>>2, col offset = c4*4
    int hh = c4 >> 2;
    #pragma unroll
    for (int rp = 0; rp < 8; rp++) {
        int row = rg * 8 + rp;
        float inv = sS[row * 8 + hh];
        float f0, f1, f2, f3;
        unpack2(acc[rp][0], f0, f1);
        unpack2(acc[rp][1], f2, f3);
        float4 o = make_float4(fmaxf(f0 * inv, 0.f), fmaxf(f1 * inv, 0.f),
                               fmaxf(f2 * inv, 0.f), fmaxf(f3 * inv, 0.f));
        *(float4*)&hprime[((size_t)b * NN + i0 + row) * 128 + c4 * 4] = o;
    }
}

// ============================================================
// Kernel 4: alpha[b,h,i,j] = adj[b,i,j] * p_h[j] * invS[i][h]
// grid 512 (b * 64 row-tiles of 16 rows), 256 threads
// ============================================================
__global__ __launch_bounds__(256) void gat_alpha(const int* __restrict__ adj,
                                                 float* __restrict__ alpha) {
    __shared__ float sInv[16 * 8];
    int tid = threadIdx.x;
    int b = blockIdx.x >> 6;
    int i0 = (blockIdx.x & 63) * 16;

    // p for this thread's 4 j-columns, all 8 heads, in registers
    float4 P[8];
    #pragma unroll
    for (int h = 0; h < 8; h++)
        P[h] = ((const float4*)(g_p + ((size_t)(b * HH + h)) * NN))[tid];

    if (tid < 128) sInv[tid] = g_invS[((size_t)b * NN + i0) * 8 + tid];
    __syncthreads();

    for (int r = 0; r < 16; r++) {
        int i = i0 + r;
        int4 av = *(const int4*)(adj + ((size_t)b * NN + i) * NN + tid * 4);
        float m0 = (float)av.x, m1 = (float)av.y;
        float m2 = (float)av.z, m3 = (float)av.w;
        #pragma unroll
        for (int h = 0; h < 8; h++) {
            float inv = sInv[r * 8 + h];
            float4 o = make_float4(m0 * (P[h].x * inv), m1 * (P[h].y * inv),
                                   m2 * (P[h].z * inv), m3 * (P[h].w * inv));
            __stwt((float4*)&alpha[(((size_t)(b * HH + h)) * NN + i) * NN + tid * 4], o);
        }
    }
}

// ============================================================
extern "C" void kernel_launch(void* const* d_in, const int* in_sizes, int n_in,
                              void* d_out, int out_size) {
    const float* x   = (const float*)d_in[0];   // (8,1024,25)
    const int*   adj = (const int*)  d_in[1];   // (8,1024,1024)
    const float* W   = (const float*)d_in[2];   // (8,25,16)
    const float* a   = (const float*)d_in[3];   // (8,32,1)

    float* out    = (float*)d_out;
    float* hprime = out;                                 // (8,1024,128)
    float* alpha  = out + (size_t)BB * NN * HH * DD;     // (8,8,1024,1024)

    const int gemm_smem = (64 * 128 + 4 * 64 * 8 + 8 * NN + 32 * 8) * 4;  // ~73KB
    cudaFuncSetAttribute(gat_gemm, cudaFuncAttributeMaxDynamicSharedMemorySize, gemm_smem);

    gat_prep<<<BB * (NN / 32), 256>>>(x, W, a);
    gat_pexp<<<BB * HH, 256>>>();
    gat_gemm<<<BB * 32, 128, gemm_smem>>>(adj, hprime);
    gat_alpha<<<BB * 64, 256>>>(adj, alpha);
}